// round 7
// baseline (speedup 1.0000x reference)
#include <cuda_runtime.h>
#include <cuda_bf16.h>
#include <math.h>
#include <stdint.h>

#define E_ 400000
#define NN_ 50000
#define B_ 50

// ---------------- device scratch (no allocs allowed) ----------------
__device__ float g_mail[NN_ * 64];
__device__ float g_ecomb[B_ * 64];
__device__ float g_ncomb[B_ * 64];
__device__ float g_gbias_e[B_ * 256];
__device__ float g_gbias_n[B_ * 256];
// pre-split weights, K-major concat (grepr segment folded into gbias)
__device__ __align__(16) __nv_bfloat16 g_Whi_e[256 * 256];
__device__ __align__(16) __nv_bfloat16 g_Wlo_e[256 * 256];
__device__ __align__(16) __nv_bfloat16 g_Whi_n[256 * 192];
__device__ __align__(16) __nv_bfloat16 g_Wlo_n[256 * 192];
// pre-split activations (everything the GEMMs consume)
__device__ __align__(16) __nv_bfloat16 g_nf_hi[NN_ * 64];
__device__ __align__(16) __nv_bfloat16 g_nf_lo[NN_ * 64];
__device__ __align__(16) __nv_bfloat16 g_nh_hi[NN_ * 64];
__device__ __align__(16) __nv_bfloat16 g_nh_lo[NN_ * 64];
__device__ __align__(16) __nv_bfloat16 g_ml_hi[NN_ * 64];
__device__ __align__(16) __nv_bfloat16 g_ml_lo[NN_ * 64];
__device__ __align__(16) __nv_bfloat16 g_ef_hi[E_ * 64];
__device__ __align__(16) __nv_bfloat16 g_ef_lo[E_ * 64];
__device__ __align__(16) __nv_bfloat16 g_eh_hi[E_ * 64];
__device__ __align__(16) __nv_bfloat16 g_eh_lo[E_ * 64];

// ---------------- smem layout (bytes); rows padded to 80 B ----------------
#define OFF_BIAS 0                     // 256 f32
#define OFF_RSUM 1024                  // 128 f32
#define OFF_GB   1536                  // 2 x 256 f32 per-graph gate bias
#define OFF_A    3584                  // A[buf][hl]: 64*80 = 5120 each
#define ABUF(buf, hl) (OFF_A + ((buf) * 2 + (hl)) * 5120)
#define OFF_B    24064                 // B[buf][hl]: 256*80 = 20480 each
#define BBUF(buf, hl) (OFF_B + ((buf) * 2 + (hl)) * 20480)
#define SMEM_SZ  105984
#define OFF_GATES 3584                 // overlay after GEMM: 64 x 260 f32

// ---------------- PTX helpers (baseline sm_80-class only) ----------------
__device__ __forceinline__ uint32_t smem_u32(const void* p) {
    uint32_t a;
    asm("{ .reg .u64 t; cvta.to.shared.u64 t, %1; cvt.u32.u64 %0, t; }" : "=r"(a) : "l"(p));
    return a;
}
#define CP_ASYNC16(dst, src) \
    asm volatile("cp.async.ca.shared.global [%0], [%1], 16;" :: "r"(dst), "l"(src))
#define CP_COMMIT() asm volatile("cp.async.commit_group;" ::: "memory")
#define CP_WAIT0()  asm volatile("cp.async.wait_group 0;" ::: "memory")

__device__ __forceinline__ void ldsm4(uint32_t* r, uint32_t a) {
    asm volatile("ldmatrix.sync.aligned.m8n8.x4.shared.b16 {%0,%1,%2,%3}, [%4];"
        : "=r"(r[0]), "=r"(r[1]), "=r"(r[2]), "=r"(r[3]) : "r"(a));
}
__device__ __forceinline__ void mma16816(float* d, const uint32_t* a, uint32_t b0, uint32_t b1) {
    asm volatile("mma.sync.aligned.m16n8k16.row.col.f32.bf16.bf16.f32 "
        "{%0,%1,%2,%3},{%4,%5,%6,%7},{%8,%9},{%0,%1,%2,%3};"
        : "+f"(d[0]), "+f"(d[1]), "+f"(d[2]), "+f"(d[3])
        : "r"(a[0]), "r"(a[1]), "r"(a[2]), "r"(a[3]), "r"(b0), "r"(b1));
}

// ---------------- math helpers ----------------
__device__ __forceinline__ float sigm(float x) { return 1.0f / (1.0f + __expf(-x)); }
__device__ __forceinline__ float tanh_(float x) {
    return __fdividef(2.0f, 1.0f + __expf(-2.0f * x)) - 1.0f;
}

// ---------------- staging (all cp.async, 32-wide K chunks) ----------------
// A chunk: 64 rows x 32 k, hi+lo pre-split bf16. 2 cp.async per thread.
template <int MODE>
__device__ __forceinline__ void issue_A(uint32_t smb, int oh, int ol,
    int c, int m0, int Mrows, int tid,
    const int* __restrict__ srcI, const int* __restrict__ dstI)
{
    const int s = c >> 1, half = c & 1;
    #pragma unroll
    for (int t = 0; t < 2; ++t) {
        int idx = tid + t * 256;
        int rl = idx >> 3, u = idx & 7;
        int grow = m0 + rl;
        if (grow >= Mrows) grow = Mrows - 1;
        const __nv_bfloat16 *hi, *lo;
        size_t ridx;
        if (MODE == 0) {
            if (s == 0)      { hi = g_ef_hi; lo = g_ef_lo; ridx = (size_t)grow; }
            else if (s == 1) { hi = g_nf_hi; lo = g_nf_lo; ridx = (size_t)srcI[grow]; }
            else if (s == 2) { hi = g_nf_hi; lo = g_nf_lo; ridx = (size_t)dstI[grow]; }
            else             { hi = g_eh_hi; lo = g_eh_lo; ridx = (size_t)grow; }
        } else {
            if (s == 0)      { hi = g_nf_hi; lo = g_nf_lo; }
            else if (s == 1) { hi = g_ml_hi; lo = g_ml_lo; }
            else             { hi = g_nh_hi; lo = g_nh_lo; }
            ridx = (size_t)grow;
        }
        const __nv_bfloat16* base = (u < 4) ? hi : lo;
        int off = (u < 4) ? oh : ol;
        int q = u & 3;
        CP_ASYNC16(smb + off + rl * 80 + q * 16,
                   (const char*)(base + ridx * 64 + half * 32 + q * 8));
    }
}

// B chunk: 256 gates x 32 k, hi+lo. 8 cp.async per thread.
__device__ __forceinline__ void issue_B(uint32_t smb, int oh, int ol,
    const __nv_bfloat16* __restrict__ Whi, const __nv_bfloat16* __restrict__ Wlo,
    int KTOT, int c, int tid)
{
    #pragma unroll
    for (int t = 0; t < 4; ++t) {
        int idx = tid + t * 256;
        int g = idx >> 2, s16 = idx & 3;
        CP_ASYNC16(smb + oh + g * 80 + s16 * 16,
                   (const char*)(Whi + (size_t)g * KTOT + c * 32 + s16 * 8));
    }
    #pragma unroll
    for (int t = 0; t < 4; ++t) {
        int idx = tid + t * 256;
        int g = idx >> 2, s16 = idx & 3;
        CP_ASYNC16(smb + ol + g * 80 + s16 * 16,
                   (const char*)(Wlo + (size_t)g * KTOT + c * 32 + s16 * 8));
    }
}

// merged 3-pass mma over one K=32 chunk; warp tile 32x64
__device__ __forceinline__ void compute32(uint32_t smb, int aHi, int aLo, int bHi, int bLo,
                                          uint32_t aoff, uint32_t boff, float (&acc)[2][8][4])
{
    #pragma unroll
    for (int kt = 0; kt < 2; ++kt) {
        uint32_t b4[4][4];
        #pragma unroll
        for (int g = 0; g < 4; ++g) ldsm4(b4[g], smb + bHi + boff + g * 1280 + kt * 32);
        #pragma unroll
        for (int mt = 0; mt < 2; ++mt) {
            uint32_t a[4];
            ldsm4(a, smb + aHi + aoff + mt * 1280 + kt * 32);
            #pragma unroll
            for (int g = 0; g < 4; ++g) {
                mma16816(acc[mt][2 * g],     a, b4[g][0], b4[g][2]);
                mma16816(acc[mt][2 * g + 1], a, b4[g][1], b4[g][3]);
            }
            ldsm4(a, smb + aLo + aoff + mt * 1280 + kt * 32);
            #pragma unroll
            for (int g = 0; g < 4; ++g) {
                mma16816(acc[mt][2 * g],     a, b4[g][0], b4[g][2]);
                mma16816(acc[mt][2 * g + 1], a, b4[g][1], b4[g][3]);
            }
        }
    }
    #pragma unroll
    for (int kt = 0; kt < 2; ++kt) {
        uint32_t b4[4][4];
        #pragma unroll
        for (int g = 0; g < 4; ++g) ldsm4(b4[g], smb + bLo + boff + g * 1280 + kt * 32);
        #pragma unroll
        for (int mt = 0; mt < 2; ++mt) {
            uint32_t a[4];
            ldsm4(a, smb + aHi + aoff + mt * 1280 + kt * 32);
            #pragma unroll
            for (int g = 0; g < 4; ++g) {
                mma16816(acc[mt][2 * g],     a, b4[g][0], b4[g][2]);
                mma16816(acc[mt][2 * g + 1], a, b4[g][1], b4[g][3]);
            }
        }
    }
}

// MODE 0: edge (K=256: ef | nf[src] | nf[dst] | eh), MODE 1: node (K=192: nf | mail | nh)
template <int MODE>
__global__ void __launch_bounds__(256, 2)
lstm_mma_kernel(const float* __restrict__ c_in,
                const float* __restrict__ bih,
                const float* __restrict__ bhh,
                const int* __restrict__ srcI,
                const int* __restrict__ dstI,
                const int* __restrict__ rgraph,
                float* __restrict__ out_r,
                float* __restrict__ out_h,
                float* __restrict__ out_c,
                int Mrows)
{
    constexpr int KTOT = (MODE == 0) ? 256 : 192;
    constexpr int NC = KTOT / 32;
    extern __shared__ char sm[];
    const uint32_t smb = smem_u32(sm);
    float* bias_s  = (float*)(sm + OFF_BIAS);
    float* rsum    = (float*)(sm + OFF_RSUM);
    float* gb_s    = (float*)(sm + OFF_GB);
    float* gates_s = (float*)(sm + OFF_GATES);

    const int tid = threadIdx.x;
    const int lane = tid & 31;
    const int wid = tid >> 5;
    const int m0 = blockIdx.x * 64;
    const __nv_bfloat16* Whi = (MODE == 0) ? g_Whi_e : g_Whi_n;
    const __nv_bfloat16* Wlo = (MODE == 0) ? g_Wlo_e : g_Wlo_n;
    const float* gbias = (MODE == 0) ? g_gbias_e : g_gbias_n;

    bias_s[tid] = bih[tid] + bhh[tid];
    if (tid < 128) rsum[tid] = 0.f;

    const int gfirst = rgraph[m0];
    int mlast = (m0 + 63 < Mrows) ? (m0 + 63) : (Mrows - 1);
    const int glast = rgraph[mlast];
    gb_s[tid]       = gbias[(size_t)gfirst * 256 + tid];
    gb_s[256 + tid] = gbias[(size_t)glast * 256 + tid];

    // prologue: chunk 0
    issue_A<MODE>(smb, ABUF(0, 0), ABUF(0, 1), 0, m0, Mrows, tid, srcI, dstI);
    issue_B(smb, BBUF(0, 0), BBUF(0, 1), Whi, Wlo, KTOT, 0, tid);
    CP_COMMIT();
    CP_WAIT0();
    __syncthreads();

    float acc[2][8][4];
    #pragma unroll
    for (int i = 0; i < 2; ++i)
        #pragma unroll
        for (int j = 0; j < 8; ++j)
            #pragma unroll
            for (int k = 0; k < 4; ++k) acc[i][j][k] = 0.f;

    const int wm = wid & 1, wn = wid >> 1;
    const uint32_t aoff = (uint32_t)((wm * 32 + (lane & 15)) * 80 + (lane >> 4) * 16);
    const uint32_t boff = (uint32_t)(wn * 5120 + (lane & 15) * 80 + (lane >> 4) * 16);

    #pragma unroll 1
    for (int c = 0; c < NC; ++c) {
        const int cur = c & 1, nxt = cur ^ 1;
        const bool have_next = (c + 1 < NC);
        if (have_next) {
            issue_A<MODE>(smb, ABUF(nxt, 0), ABUF(nxt, 1), c + 1, m0, Mrows, tid, srcI, dstI);
            issue_B(smb, BBUF(nxt, 0), BBUF(nxt, 1), Whi, Wlo, KTOT, c + 1, tid);
            CP_COMMIT();
        }
        compute32(smb, ABUF(cur, 0), ABUF(cur, 1), BBUF(cur, 0), BBUF(cur, 1), aoff, boff, acc);
        if (have_next) CP_WAIT0();
        __syncthreads();
    }

    // ---- acc -> gates_s[64][260] (overlays A/B smem) ----
    #pragma unroll
    for (int mt = 0; mt < 2; ++mt) {
        int r0 = wm * 32 + mt * 16 + (lane >> 2);
        #pragma unroll
        for (int nt = 0; nt < 8; ++nt) {
            int nc = wn * 64 + nt * 8 + (lane & 3) * 2;
            *(float2*)&gates_s[r0 * 260 + nc]       = make_float2(acc[mt][nt][0], acc[mt][nt][1]);
            *(float2*)&gates_s[(r0 + 8) * 260 + nc] = make_float2(acc[mt][nt][2], acc[mt][nt][3]);
        }
    }
    __syncthreads();

    // ---- fused LSTM pointwise + mailbox scatter + per-graph sums ----
    const int d = tid & 63;
    const float bi = bias_s[d], bf = bias_s[64 + d], bg = bias_s[128 + d], bo = bias_s[192 + d];
    float a0 = 0.f, a1 = 0.f;
    #pragma unroll 4
    for (int it = 0; it < 16; ++it) {
        int ml = it * 4 + (tid >> 6);
        int grow = m0 + ml;
        if (grow < Mrows) {
            int sel = (rgraph[grow] == gfirst) ? 0 : 256;
            float gi = gates_s[ml * 260 + d]       + bi + gb_s[sel + d];
            float gf = gates_s[ml * 260 + 64 + d]  + bf + gb_s[sel + 64 + d];
            float gg = gates_s[ml * 260 + 128 + d] + bg + gb_s[sel + 128 + d];
            float go = gates_s[ml * 260 + 192 + d] + bo + gb_s[sel + 192 + d];
            float c2 = sigm(gf) * c_in[(size_t)grow * 64 + d] + sigm(gi) * tanh_(gg);
            float h = sigm(go) * tanh_(c2);
            float r = fmaxf(h, 0.f);
            out_r[(size_t)grow * 64 + d] = r;
            out_h[(size_t)grow * 64 + d] = h;
            out_c[(size_t)grow * 64 + d] = c2;
            if (MODE == 0) atomicAdd(&g_mail[(size_t)dstI[grow] * 64 + d], r);
            if (sel == 0) a0 += r; else a1 += r;
        }
    }
    atomicAdd(&rsum[d], a0);
    atomicAdd(&rsum[64 + d], a1);
    __syncthreads();
    float* comb = (MODE == 0) ? g_ecomb : g_ncomb;
    if (tid < 64) atomicAdd(&comb[(size_t)gfirst * 64 + tid], rsum[tid]);
    else if (tid < 128 && glast != gfirst)
        atomicAdd(&comb[(size_t)glast * 64 + (tid - 64)], rsum[tid]);
}

// ---------------- prep kernels ----------------
__device__ __forceinline__ void split_to(float v, __nv_bfloat16* hi, __nv_bfloat16* lo, size_t i) {
    __nv_bfloat16 h = __float2bfloat16(v);
    hi[i] = h;
    lo[i] = __float2bfloat16(v - __bfloat162float(h));
}

// fused: split ef/eh/nf/nh + zero scratch
__global__ void prep_kernel(const float* __restrict__ ef, const float* __restrict__ eh,
                            const float* __restrict__ nf, const float* __restrict__ nh)
{
    size_t i = (size_t)blockIdx.x * 256 + threadIdx.x;
    if (i < (size_t)E_ * 64) {
        split_to(ef[i], g_ef_hi, g_ef_lo, i);
        split_to(eh[i], g_eh_hi, g_eh_lo, i);
    }
    if (i < (size_t)NN_ * 64) {
        split_to(nf[i], g_nf_hi, g_nf_lo, i);
        split_to(nh[i], g_nh_hi, g_nh_lo, i);
        g_mail[i] = 0.f;
    }
    if (i < B_ * 64) { g_ecomb[i] = 0.f; g_ncomb[i] = 0.f; }
}

// W pre-split, K-major, grepr segment removed
__global__ void splitw_kernel(const float* __restrict__ Wih_e, const float* __restrict__ Whh_e,
                              const float* __restrict__ Wih_n, const float* __restrict__ Whh_n)
{
    int i = blockIdx.x * 256 + threadIdx.x;
    if (i < 256 * 256) {
        int g = i >> 8, k = i & 255;
        float v = (k < 192) ? Wih_e[g * 256 + k] : Whh_e[g * 64 + (k - 192)];
        split_to(v, g_Whi_e, g_Wlo_e, i);
    }
    if (i < 256 * 192) {
        int g = i / 192, k = i - g * 192;
        float v = (k < 128) ? Wih_n[g * 192 + k] : Whh_n[g * 64 + (k - 128)];
        split_to(v, g_Whi_n, g_Wlo_n, i);
    }
}

// per-graph gate bias: grepr @ Wseg
__global__ void gbias_kernel(const float* __restrict__ grepr,
                             const float* __restrict__ Wih_e,
                             const float* __restrict__ Wih_n)
{
    __shared__ float gsh[64];
    const int b = blockIdx.x, tid = threadIdx.x;
    if (tid < 64) gsh[tid] = grepr[b * 64 + tid];
    __syncthreads();
    float ae = 0.f, an = 0.f;
    #pragma unroll 8
    for (int k = 0; k < 64; ++k) {
        ae += gsh[k] * Wih_e[tid * 256 + 192 + k];
        an += gsh[k] * Wih_n[tid * 192 + 128 + k];
    }
    g_gbias_e[b * 256 + tid] = ae;
    g_gbias_n[b * 256 + tid] = an;
}

__global__ void split_mail_kernel()
{
    int i = blockIdx.x * 256 + threadIdx.x;
    if (i < NN_ * 64) {
        float v = g_mail[i];
        split_to(v, g_ml_hi, g_ml_lo, i);
    }
}

// ---------------- graph-level LSTM (B=50) ----------------
__global__ void graph_lstm_kernel(
    const float* __restrict__ grepr,
    const float* __restrict__ h_in,
    const float* __restrict__ c_in,
    const float* __restrict__ Wih,
    const float* __restrict__ Whh,
    const float* __restrict__ bih,
    const float* __restrict__ bhh,
    float* __restrict__ out_r,
    float* __restrict__ out_h,
    float* __restrict__ out_c)
{
    __shared__ float xu[256];
    __shared__ float gs[256];
    const int b = blockIdx.x;
    const int tid = threadIdx.x;

    if (tid < 64)       xu[tid] = g_ncomb[b * 64 + tid];
    else if (tid < 128) xu[tid] = g_ecomb[b * 64 + (tid - 64)];
    else if (tid < 192) xu[tid] = grepr[b * 64 + (tid - 128)];
    else                xu[tid] = h_in[b * 64 + (tid - 192)];
    __syncthreads();

    float a = bih[tid] + bhh[tid];
    const float* wih_row = Wih + (size_t)tid * 192;
    #pragma unroll 8
    for (int k4 = 0; k4 < 48; ++k4) {
        float4 w = *(const float4*)&wih_row[k4 * 4];
        a += w.x * xu[k4 * 4] + w.y * xu[k4 * 4 + 1] + w.z * xu[k4 * 4 + 2] + w.w * xu[k4 * 4 + 3];
    }
    const float* whh_row = Whh + (size_t)tid * 64;
    #pragma unroll 8
    for (int k4 = 0; k4 < 16; ++k4) {
        float4 w = *(const float4*)&whh_row[k4 * 4];
        a += w.x * xu[192 + k4 * 4] + w.y * xu[192 + k4 * 4 + 1]
           + w.z * xu[192 + k4 * 4 + 2] + w.w * xu[192 + k4 * 4 + 3];
    }
    gs[tid] = a;
    __syncthreads();

    if (tid < 64) {
        float gi = gs[tid], gf = gs[64 + tid], gg = gs[128 + tid], go = gs[192 + tid];
        float c2 = sigm(gf) * c_in[b * 64 + tid] + sigm(gi) * tanh_(gg);
        float h = sigm(go) * tanh_(c2);
        out_r[b * 64 + tid] = fmaxf(h, 0.f);
        out_h[b * 64 + tid] = h;
        out_c[b * 64 + tid] = c2;
    }
}

extern "C" void kernel_launch(void* const* d_in, const int* in_sizes, int n_in,
                              void* d_out, int out_size)
{
    const float* edge_feat  = (const float*)d_in[0];
    const float* node_feat  = (const float*)d_in[1];
    const float* g_repr     = (const float*)d_in[2];
    const float* edge_h     = (const float*)d_in[3];
    const float* edge_c     = (const float*)d_in[4];
    const float* node_h     = (const float*)d_in[5];
    const float* node_c     = (const float*)d_in[6];
    const float* graph_h    = (const float*)d_in[7];
    const float* graph_c    = (const float*)d_in[8];
    const float* Wih_e      = (const float*)d_in[9];
    const float* Whh_e      = (const float*)d_in[10];
    const float* bih_e      = (const float*)d_in[11];
    const float* bhh_e      = (const float*)d_in[12];
    const float* Wih_n      = (const float*)d_in[13];
    const float* Whh_n      = (const float*)d_in[14];
    const float* bih_n      = (const float*)d_in[15];
    const float* bhh_n      = (const float*)d_in[16];
    const float* Wih_u      = (const float*)d_in[17];
    const float* Whh_u      = (const float*)d_in[18];
    const float* bih_u      = (const float*)d_in[19];
    const float* bhh_u      = (const float*)d_in[20];
    const int*   src        = (const int*)d_in[21];
    const int*   dst        = (const int*)d_in[22];
    const int*   edge_graph = (const int*)d_in[23];
    const int*   node_graph = (const int*)d_in[24];

    float* out = (float*)d_out;
    const size_t ED = (size_t)E_ * 64;
    const size_t ND = (size_t)NN_ * 64;
    const size_t BD = (size_t)B_ * 64;
    float* e_out = out;
    float* h_e   = out + ED;
    float* c_e   = out + 2 * ED;
    float* n_out = out + 3 * ED;
    float* h_n   = n_out + ND;
    float* c_n   = n_out + 2 * ND;
    float* u_out = n_out + 3 * ND;
    float* h_u   = u_out + BD;
    float* c_u   = u_out + 2 * BD;

    cudaFuncSetAttribute(lstm_mma_kernel<0>, cudaFuncAttributeMaxDynamicSharedMemorySize, SMEM_SZ);
    cudaFuncSetAttribute(lstm_mma_kernel<1>, cudaFuncAttributeMaxDynamicSharedMemorySize, SMEM_SZ);

    // 1) prep: activation splits + scratch zero (fused), weight split, gbias
    prep_kernel<<<(int)(((size_t)E_ * 64 + 255) / 256), 256>>>(edge_feat, edge_h, node_feat, node_h);
    splitw_kernel<<<256, 256>>>(Wih_e, Whh_e, Wih_n, Whh_n);
    gbias_kernel<<<B_, 256>>>(g_repr, Wih_e, Wih_n);

    // 2) edge LSTM (K=256, 64-row tiles, 2 CTA/SM) + mailbox scatter + e_comb
    lstm_mma_kernel<0><<<E_ / 64, 256, SMEM_SZ>>>(
        edge_c, bih_e, bhh_e, src, dst, edge_graph, e_out, h_e, c_e, E_);

    // 3) split mail, then node LSTM (K=192) + n_comb
    split_mail_kernel<<<(NN_ * 64 + 255) / 256, 256>>>();
    lstm_mma_kernel<1><<<(NN_ + 63) / 64, 256, SMEM_SZ>>>(
        node_c, bih_n, bhh_n, nullptr, nullptr, node_graph, n_out, h_n, c_n, NN_);

    // 4) graph LSTM
    graph_lstm_kernel<<<B_, 256>>>(
        g_repr, graph_h, graph_c,
        Wih_u, Whh_u, bih_u, bhh_u,
        u_out, h_u, c_u);
}

// round 8
// speedup vs baseline: 1.3194x; 1.3194x over previous
#include <cuda_runtime.h>
#include <cuda_fp16.h>
#include <math.h>
#include <stdint.h>

#define E_ 400000
#define NN_ 50000
#define B_ 50

// ---------------- device scratch (no allocs allowed) ----------------
__device__ float g_mail[NN_ * 64];
__device__ float g_ecomb[B_ * 64];
__device__ float g_ncomb[B_ * 64];
__device__ float g_gbias_e[B_ * 256];
__device__ float g_gbias_n[B_ * 256];
// fp16 weights (single rounding; K-major concat, grepr segment folded into gbias)
__device__ __align__(16) __half g_W_e[256 * 256];
__device__ __align__(16) __half g_W_n[256 * 192];
// fp16 hi/lo pre-split activations
__device__ __align__(16) __half g_nf_hi[NN_ * 64];
__device__ __align__(16) __half g_nf_lo[NN_ * 64];
__device__ __align__(16) __half g_nh_hi[NN_ * 64];
__device__ __align__(16) __half g_nh_lo[NN_ * 64];
__device__ __align__(16) __half g_ml_hi[NN_ * 64];
__device__ __align__(16) __half g_ml_lo[NN_ * 64];
__device__ __align__(16) __half g_ef_hi[E_ * 64];
__device__ __align__(16) __half g_ef_lo[E_ * 64];
__device__ __align__(16) __half g_eh_hi[E_ * 64];
__device__ __align__(16) __half g_eh_lo[E_ * 64];

// ---------------- smem layout (bytes); rows padded to 80 B ----------------
#define OFF_BIAS 0                     // 256 f32
#define OFF_RSUM 1024                  // 128 f32
#define OFF_GB   1536                  // 2 x 256 f32 per-graph gate bias
#define OFF_A    3584                  // A[buf][hl]: 64*80 = 5120 each
#define ABUF(buf, hl) (OFF_A + ((buf) * 2 + (hl)) * 5120)
#define OFF_B    24064                 // B[buf]: 256*80 = 20480 each (hi only)
#define BBUF(buf) (OFF_B + (buf) * 20480)
#define OFF_GATES 3584                 // overlay after GEMM: 64 x 260 f32
#define SMEM_SZ  70144

// ---------------- PTX helpers (baseline sm_80-class only) ----------------
__device__ __forceinline__ uint32_t smem_u32(const void* p) {
    uint32_t a;
    asm("{ .reg .u64 t; cvta.to.shared.u64 t, %1; cvt.u32.u64 %0, t; }" : "=r"(a) : "l"(p));
    return a;
}
#define CP_ASYNC16(dst, src) \
    asm volatile("cp.async.ca.shared.global [%0], [%1], 16;" :: "r"(dst), "l"(src))
#define CP_COMMIT() asm volatile("cp.async.commit_group;" ::: "memory")
#define CP_WAIT0()  asm volatile("cp.async.wait_group 0;" ::: "memory")

__device__ __forceinline__ void ldsm4(uint32_t* r, uint32_t a) {
    asm volatile("ldmatrix.sync.aligned.m8n8.x4.shared.b16 {%0,%1,%2,%3}, [%4];"
        : "=r"(r[0]), "=r"(r[1]), "=r"(r[2]), "=r"(r[3]) : "r"(a));
}
__device__ __forceinline__ void mma16816(float* d, const uint32_t* a, uint32_t b0, uint32_t b1) {
    asm volatile("mma.sync.aligned.m16n8k16.row.col.f32.f16.f16.f32 "
        "{%0,%1,%2,%3},{%4,%5,%6,%7},{%8,%9},{%0,%1,%2,%3};"
        : "+f"(d[0]), "+f"(d[1]), "+f"(d[2]), "+f"(d[3])
        : "r"(a[0]), "r"(a[1]), "r"(a[2]), "r"(a[3]), "r"(b0), "r"(b1));
}

// ---------------- math helpers ----------------
__device__ __forceinline__ float sigm(float x) { return 1.0f / (1.0f + __expf(-x)); }
__device__ __forceinline__ float tanh_(float x) {
    return __fdividef(2.0f, 1.0f + __expf(-2.0f * x)) - 1.0f;
}

// ---------------- staging (all cp.async, 32-wide K chunks) ----------------
// A chunk: 64 rows x 32 k, fp16 hi+lo. 2 cp.async per thread.
template <int MODE>
__device__ __forceinline__ void issue_A(uint32_t smb, int oh, int ol,
    int c, int m0, int Mrows, int tid,
    const int* __restrict__ srcI, const int* __restrict__ dstI)
{
    const int s = c >> 1, half = c & 1;
    #pragma unroll
    for (int t = 0; t < 2; ++t) {
        int idx = tid + t * 256;
        int rl = idx >> 3, u = idx & 7;
        int grow = m0 + rl;
        if (grow >= Mrows) grow = Mrows - 1;
        const __half *hi, *lo;
        size_t ridx;
        if (MODE == 0) {
            if (s == 0)      { hi = g_ef_hi; lo = g_ef_lo; ridx = (size_t)grow; }
            else if (s == 1) { hi = g_nf_hi; lo = g_nf_lo; ridx = (size_t)srcI[grow]; }
            else if (s == 2) { hi = g_nf_hi; lo = g_nf_lo; ridx = (size_t)dstI[grow]; }
            else             { hi = g_eh_hi; lo = g_eh_lo; ridx = (size_t)grow; }
        } else {
            if (s == 0)      { hi = g_nf_hi; lo = g_nf_lo; }
            else if (s == 1) { hi = g_ml_hi; lo = g_ml_lo; }
            else             { hi = g_nh_hi; lo = g_nh_lo; }
            ridx = (size_t)grow;
        }
        const __half* base = (u < 4) ? hi : lo;
        int off = (u < 4) ? oh : ol;
        int q = u & 3;
        CP_ASYNC16(smb + off + rl * 80 + q * 16,
                   (const char*)(base + ridx * 64 + half * 32 + q * 8));
    }
}

// B chunk: 256 gates x 32 k (hi only). 4 cp.async per thread.
__device__ __forceinline__ void issue_B(uint32_t smb, int ob,
    const __half* __restrict__ W, int KTOT, int c, int tid)
{
    #pragma unroll
    for (int t = 0; t < 4; ++t) {
        int idx = tid + t * 256;
        int g = idx >> 2, s16 = idx & 3;
        CP_ASYNC16(smb + ob + g * 80 + s16 * 16,
                   (const char*)(W + (size_t)g * KTOT + c * 32 + s16 * 8));
    }
}

// merged 2-pass fp16 mma over one K=32 chunk; warp tile 32x64 (B frags reused)
__device__ __forceinline__ void compute32(uint32_t smb, int aHi, int aLo, int bB,
                                          uint32_t aoff, uint32_t boff, float (&acc)[2][8][4])
{
    #pragma unroll
    for (int kt = 0; kt < 2; ++kt) {
        uint32_t b4[4][4];
        #pragma unroll
        for (int g = 0; g < 4; ++g) ldsm4(b4[g], smb + bB + boff + g * 1280 + kt * 32);
        #pragma unroll
        for (int mt = 0; mt < 2; ++mt) {
            uint32_t a[4];
            ldsm4(a, smb + aHi + aoff + mt * 1280 + kt * 32);
            #pragma unroll
            for (int g = 0; g < 4; ++g) {
                mma16816(acc[mt][2 * g],     a, b4[g][0], b4[g][2]);
                mma16816(acc[mt][2 * g + 1], a, b4[g][1], b4[g][3]);
            }
            ldsm4(a, smb + aLo + aoff + mt * 1280 + kt * 32);
            #pragma unroll
            for (int g = 0; g < 4; ++g) {
                mma16816(acc[mt][2 * g],     a, b4[g][0], b4[g][2]);
                mma16816(acc[mt][2 * g + 1], a, b4[g][1], b4[g][3]);
            }
        }
    }
}

// MODE 0: edge (K=256: ef | nf[src] | nf[dst] | eh), MODE 1: node (K=192: nf | mail | nh)
template <int MODE>
__global__ void __launch_bounds__(256, 2)
lstm_mma_kernel(const float* __restrict__ c_in,
                const float* __restrict__ bih,
                const float* __restrict__ bhh,
                const int* __restrict__ srcI,
                const int* __restrict__ dstI,
                const int* __restrict__ rgraph,
                float* __restrict__ out_r,
                float* __restrict__ out_h,
                float* __restrict__ out_c,
                int Mrows)
{
    constexpr int KTOT = (MODE == 0) ? 256 : 192;
    constexpr int NC = KTOT / 32;
    extern __shared__ char sm[];
    const uint32_t smb = smem_u32(sm);
    float* bias_s  = (float*)(sm + OFF_BIAS);
    float* rsum    = (float*)(sm + OFF_RSUM);
    float* gb_s    = (float*)(sm + OFF_GB);
    float* gates_s = (float*)(sm + OFF_GATES);

    const int tid = threadIdx.x;
    const int lane = tid & 31;
    const int wid = tid >> 5;
    const int m0 = blockIdx.x * 64;
    const __half* W = (MODE == 0) ? g_W_e : g_W_n;
    const float* gbias = (MODE == 0) ? g_gbias_e : g_gbias_n;

    bias_s[tid] = bih[tid] + bhh[tid];
    if (tid < 128) rsum[tid] = 0.f;

    const int gfirst = rgraph[m0];
    int mlast = (m0 + 63 < Mrows) ? (m0 + 63) : (Mrows - 1);
    const int glast = rgraph[mlast];
    gb_s[tid]       = gbias[(size_t)gfirst * 256 + tid];
    gb_s[256 + tid] = gbias[(size_t)glast * 256 + tid];

    // prologue: chunk 0
    issue_A<MODE>(smb, ABUF(0, 0), ABUF(0, 1), 0, m0, Mrows, tid, srcI, dstI);
    issue_B(smb, BBUF(0), W, KTOT, 0, tid);
    CP_COMMIT();
    CP_WAIT0();
    __syncthreads();

    float acc[2][8][4];
    #pragma unroll
    for (int i = 0; i < 2; ++i)
        #pragma unroll
        for (int j = 0; j < 8; ++j)
            #pragma unroll
            for (int k = 0; k < 4; ++k) acc[i][j][k] = 0.f;

    const int wm = wid & 1, wn = wid >> 1;
    const uint32_t aoff = (uint32_t)((wm * 32 + (lane & 15)) * 80 + (lane >> 4) * 16);
    const uint32_t boff = (uint32_t)(wn * 5120 + (lane & 15) * 80 + (lane >> 4) * 16);

    #pragma unroll 1
    for (int c = 0; c < NC; ++c) {
        const int cur = c & 1, nxt = cur ^ 1;
        const bool have_next = (c + 1 < NC);
        if (have_next) {
            issue_A<MODE>(smb, ABUF(nxt, 0), ABUF(nxt, 1), c + 1, m0, Mrows, tid, srcI, dstI);
            issue_B(smb, BBUF(nxt), W, KTOT, c + 1, tid);
            CP_COMMIT();
        }
        compute32(smb, ABUF(cur, 0), ABUF(cur, 1), BBUF(cur), aoff, boff, acc);
        if (have_next) CP_WAIT0();
        __syncthreads();
    }

    // ---- acc -> gates_s[64][260] (overlays A/B smem) ----
    #pragma unroll
    for (int mt = 0; mt < 2; ++mt) {
        int r0 = wm * 32 + mt * 16 + (lane >> 2);
        #pragma unroll
        for (int nt = 0; nt < 8; ++nt) {
            int nc = wn * 64 + nt * 8 + (lane & 3) * 2;
            *(float2*)&gates_s[r0 * 260 + nc]       = make_float2(acc[mt][nt][0], acc[mt][nt][1]);
            *(float2*)&gates_s[(r0 + 8) * 260 + nc] = make_float2(acc[mt][nt][2], acc[mt][nt][3]);
        }
    }
    __syncthreads();

    // ---- fused LSTM pointwise + mailbox scatter + per-graph sums ----
    const int d = tid & 63;
    const float bi = bias_s[d], bf = bias_s[64 + d], bg = bias_s[128 + d], bo = bias_s[192 + d];
    float a0 = 0.f, a1 = 0.f;
    #pragma unroll 4
    for (int it = 0; it < 16; ++it) {
        int ml = it * 4 + (tid >> 6);
        int grow = m0 + ml;
        if (grow < Mrows) {
            int sel = (rgraph[grow] == gfirst) ? 0 : 256;
            float gi = gates_s[ml * 260 + d]       + bi + gb_s[sel + d];
            float gf = gates_s[ml * 260 + 64 + d]  + bf + gb_s[sel + 64 + d];
            float gg = gates_s[ml * 260 + 128 + d] + bg + gb_s[sel + 128 + d];
            float go = gates_s[ml * 260 + 192 + d] + bo + gb_s[sel + 192 + d];
            float c2 = sigm(gf) * c_in[(size_t)grow * 64 + d] + sigm(gi) * tanh_(gg);
            float h = sigm(go) * tanh_(c2);
            float r = fmaxf(h, 0.f);
            out_r[(size_t)grow * 64 + d] = r;
            out_h[(size_t)grow * 64 + d] = h;
            out_c[(size_t)grow * 64 + d] = c2;
            if (MODE == 0) atomicAdd(&g_mail[(size_t)dstI[grow] * 64 + d], r);
            if (sel == 0) a0 += r; else a1 += r;
        }
    }
    atomicAdd(&rsum[d], a0);
    atomicAdd(&rsum[64 + d], a1);
    __syncthreads();
    float* comb = (MODE == 0) ? g_ecomb : g_ncomb;
    if (tid < 64) atomicAdd(&comb[(size_t)gfirst * 64 + tid], rsum[tid]);
    else if (tid < 128 && glast != gfirst)
        atomicAdd(&comb[(size_t)glast * 64 + (tid - 64)], rsum[tid]);
}

// ---------------- prep kernels ----------------
__device__ __forceinline__ void split_to(float v, __half* hi, __half* lo, size_t i) {
    __half h = __float2half_rn(v);
    hi[i] = h;
    lo[i] = __float2half_rn(v - __half2float(h));
}

// fused: split ef/eh/nf/nh to fp16 hi/lo + zero scratch
__global__ void prep_kernel(const float* __restrict__ ef, const float* __restrict__ eh,
                            const float* __restrict__ nf, const float* __restrict__ nh)
{
    size_t i = (size_t)blockIdx.x * 256 + threadIdx.x;
    if (i < (size_t)E_ * 64) {
        split_to(ef[i], g_ef_hi, g_ef_lo, i);
        split_to(eh[i], g_eh_hi, g_eh_lo, i);
    }
    if (i < (size_t)NN_ * 64) {
        split_to(nf[i], g_nf_hi, g_nf_lo, i);
        split_to(nh[i], g_nh_hi, g_nh_lo, i);
        g_mail[i] = 0.f;
    }
    if (i < B_ * 64) { g_ecomb[i] = 0.f; g_ncomb[i] = 0.f; }
}

// W -> fp16 (single rounding), K-major, grepr segment removed
__global__ void splitw_kernel(const float* __restrict__ Wih_e, const float* __restrict__ Whh_e,
                              const float* __restrict__ Wih_n, const float* __restrict__ Whh_n)
{
    int i = blockIdx.x * 256 + threadIdx.x;
    if (i < 256 * 256) {
        int g = i >> 8, k = i & 255;
        float v = (k < 192) ? Wih_e[g * 256 + k] : Whh_e[g * 64 + (k - 192)];
        g_W_e[i] = __float2half_rn(v);
    }
    if (i < 256 * 192) {
        int g = i / 192, k = i - g * 192;
        float v = (k < 128) ? Wih_n[g * 192 + k] : Whh_n[g * 64 + (k - 128)];
        g_W_n[i] = __float2half_rn(v);
    }
}

// per-graph gate bias: grepr @ Wseg (f32, exact)
__global__ void gbias_kernel(const float* __restrict__ grepr,
                             const float* __restrict__ Wih_e,
                             const float* __restrict__ Wih_n)
{
    __shared__ float gsh[64];
    const int b = blockIdx.x, tid = threadIdx.x;
    if (tid < 64) gsh[tid] = grepr[b * 64 + tid];
    __syncthreads();
    float ae = 0.f, an = 0.f;
    #pragma unroll 8
    for (int k = 0; k < 64; ++k) {
        ae += gsh[k] * Wih_e[tid * 256 + 192 + k];
        an += gsh[k] * Wih_n[tid * 192 + 128 + k];
    }
    g_gbias_e[b * 256 + tid] = ae;
    g_gbias_n[b * 256 + tid] = an;
}

__global__ void split_mail_kernel()
{
    int i = blockIdx.x * 256 + threadIdx.x;
    if (i < NN_ * 64) split_to(g_mail[i], g_ml_hi, g_ml_lo, i);
}

// ---------------- graph-level LSTM (B=50) ----------------
__global__ void graph_lstm_kernel(
    const float* __restrict__ grepr,
    const float* __restrict__ h_in,
    const float* __restrict__ c_in,
    const float* __restrict__ Wih,
    const float* __restrict__ Whh,
    const float* __restrict__ bih,
    const float* __restrict__ bhh,
    float* __restrict__ out_r,
    float* __restrict__ out_h,
    float* __restrict__ out_c)
{
    __shared__ float xu[256];
    __shared__ float gs[256];
    const int b = blockIdx.x;
    const int tid = threadIdx.x;

    if (tid < 64)       xu[tid] = g_ncomb[b * 64 + tid];
    else if (tid < 128) xu[tid] = g_ecomb[b * 64 + (tid - 64)];
    else if (tid < 192) xu[tid] = grepr[b * 64 + (tid - 128)];
    else                xu[tid] = h_in[b * 64 + (tid - 192)];
    __syncthreads();

    float a = bih[tid] + bhh[tid];
    const float* wih_row = Wih + (size_t)tid * 192;
    #pragma unroll 8
    for (int k4 = 0; k4 < 48; ++k4) {
        float4 w = *(const float4*)&wih_row[k4 * 4];
        a += w.x * xu[k4 * 4] + w.y * xu[k4 * 4 + 1] + w.z * xu[k4 * 4 + 2] + w.w * xu[k4 * 4 + 3];
    }
    const float* whh_row = Whh + (size_t)tid * 64;
    #pragma unroll 8
    for (int k4 = 0; k4 < 16; ++k4) {
        float4 w = *(const float4*)&whh_row[k4 * 4];
        a += w.x * xu[192 + k4 * 4] + w.y * xu[192 + k4 * 4 + 1]
           + w.z * xu[192 + k4 * 4 + 2] + w.w * xu[192 + k4 * 4 + 3];
    }
    gs[tid] = a;
    __syncthreads();

    if (tid < 64) {
        float gi = gs[tid], gf = gs[64 + tid], gg = gs[128 + tid], go = gs[192 + tid];
        float c2 = sigm(gf) * c_in[b * 64 + tid] + sigm(gi) * tanh_(gg);
        float h = sigm(go) * tanh_(c2);
        out_r[b * 64 + tid] = fmaxf(h, 0.f);
        out_h[b * 64 + tid] = h;
        out_c[b * 64 + tid] = c2;
    }
}

extern "C" void kernel_launch(void* const* d_in, const int* in_sizes, int n_in,
                              void* d_out, int out_size)
{
    const float* edge_feat  = (const float*)d_in[0];
    const float* node_feat  = (const float*)d_in[1];
    const float* g_repr     = (const float*)d_in[2];
    const float* edge_h     = (const float*)d_in[3];
    const float* edge_c     = (const float*)d_in[4];
    const float* node_h     = (const float*)d_in[5];
    const float* node_c     = (const float*)d_in[6];
    const float* graph_h    = (const float*)d_in[7];
    const float* graph_c    = (const float*)d_in[8];
    const float* Wih_e      = (const float*)d_in[9];
    const float* Whh_e      = (const float*)d_in[10];
    const float* bih_e      = (const float*)d_in[11];
    const float* bhh_e      = (const float*)d_in[12];
    const float* Wih_n      = (const float*)d_in[13];
    const float* Whh_n      = (const float*)d_in[14];
    const float* bih_n      = (const float*)d_in[15];
    const float* bhh_n      = (const float*)d_in[16];
    const float* Wih_u      = (const float*)d_in[17];
    const float* Whh_u      = (const float*)d_in[18];
    const float* bih_u      = (const float*)d_in[19];
    const float* bhh_u      = (const float*)d_in[20];
    const int*   src        = (const int*)d_in[21];
    const int*   dst        = (const int*)d_in[22];
    const int*   edge_graph = (const int*)d_in[23];
    const int*   node_graph = (const int*)d_in[24];

    float* out = (float*)d_out;
    const size_t ED = (size_t)E_ * 64;
    const size_t ND = (size_t)NN_ * 64;
    const size_t BD = (size_t)B_ * 64;
    float* e_out = out;
    float* h_e   = out + ED;
    float* c_e   = out + 2 * ED;
    float* n_out = out + 3 * ED;
    float* h_n   = n_out + ND;
    float* c_n   = n_out + 2 * ND;
    float* u_out = n_out + 3 * ND;
    float* h_u   = u_out + BD;
    float* c_u   = u_out + 2 * BD;

    cudaFuncSetAttribute(lstm_mma_kernel<0>, cudaFuncAttributeMaxDynamicSharedMemorySize, SMEM_SZ);
    cudaFuncSetAttribute(lstm_mma_kernel<1>, cudaFuncAttributeMaxDynamicSharedMemorySize, SMEM_SZ);

    // 1) prep: activation fp16 splits + scratch zero (fused), weight fp16, gbias
    prep_kernel<<<(int)(((size_t)E_ * 64 + 255) / 256), 256>>>(edge_feat, edge_h, node_feat, node_h);
    splitw_kernel<<<256, 256>>>(Wih_e, Whh_e, Wih_n, Whh_n);
    gbias_kernel<<<B_, 256>>>(g_repr, Wih_e, Wih_n);

    // 2) edge LSTM (fp16 2-pass, K=256) + mailbox scatter + e_comb
    lstm_mma_kernel<0><<<E_ / 64, 256, SMEM_SZ>>>(
        edge_c, bih_e, bhh_e, src, dst, edge_graph, e_out, h_e, c_e, E_);

    // 3) split mail, then node LSTM (K=192) + n_comb
    split_mail_kernel<<<(NN_ * 64 + 255) / 256, 256>>>();
    lstm_mma_kernel<1><<<(NN_ + 63) / 64, 256, SMEM_SZ>>>(
        node_c, bih_n, bhh_n, nullptr, nullptr, node_graph, n_out, h_n, c_n, NN_);

    // 4) graph LSTM
    graph_lstm_kernel<<<B_, 256>>>(
        g_repr, graph_h, graph_c,
        Wih_u, Whh_u, bih_u, bhh_u,
        u_out, h_u, c_u);
}